// round 1
// baseline (speedup 1.0000x reference)
#include <cuda_runtime.h>

#define NODES_MAX 100000
#define NPER 12
#define ROWP 16   // padded row: 16 floats = 64 B, sector-aligned

__device__ int   g_deg[NODES_MAX];
__device__ float g_dinv[NODES_MAX];
__device__ float g_y[NODES_MAX * ROWP];
__device__ float g_acc[NODES_MAX * ROWP];

// ---------------- K0: zero acc + deg ----------------
__global__ void k_zero(int n_nodes) {
    int i = blockIdx.x * blockDim.x + threadIdx.x;
    int total = n_nodes * ROWP;
    if (i < total) g_acc[i] = 0.0f;
    if (i < n_nodes) g_deg[i] = 0;
}

// ---------------- K1: degree count (int4 vectorized) ----------------
__global__ void k_deg(const int* __restrict__ dst, int E) {
    int i = blockIdx.x * blockDim.x + threadIdx.x;
    int e4 = E >> 2;
    if (i < e4) {
        int4 d = ((const int4*)dst)[i];
        atomicAdd(&g_deg[d.x], 1);
        atomicAdd(&g_deg[d.y], 1);
        atomicAdd(&g_deg[d.z], 1);
        atomicAdd(&g_deg[d.w], 1);
    } else if (i == e4) {
        for (int r = e4 * 4; r < E; r++) atomicAdd(&g_deg[dst[r]], 1);
    }
}

// ---------------- K2: dinv + scaled x into padded rows ----------------
__global__ void k_prep(const float* __restrict__ x, int n) {
    int i = blockIdx.x * blockDim.x + threadIdx.x;
    if (i >= n) return;
    float dinv = rsqrtf((float)(g_deg[i] + 1));  // +1 for self loop
    g_dinv[i] = dinv;
    const float4* xr = (const float4*)(x + (size_t)i * NPER);
    float4 a = xr[0], b = xr[1], c = xr[2];
    float4* yr = (float4*)(g_y + (size_t)i * ROWP);
    yr[0] = make_float4(a.x * dinv, a.y * dinv, a.z * dinv, a.w * dinv);
    yr[1] = make_float4(b.x * dinv, b.y * dinv, b.z * dinv, b.w * dinv);
    yr[2] = make_float4(c.x * dinv, c.y * dinv, c.z * dinv, c.w * dinv);
    yr[3] = make_float4(0.f, 0.f, 0.f, 0.f);
}

// ---------------- K3: edge scatter (the hot kernel) ----------------
__device__ __forceinline__ void red_v4(float* p, float4 v) {
    asm volatile("red.global.add.v4.f32 [%0], {%1,%2,%3,%4};"
                 :: "l"(p), "f"(v.x), "f"(v.y), "f"(v.z), "f"(v.w)
                 : "memory");
}

__global__ void k_scatter(const int* __restrict__ src, const int* __restrict__ dst, int E) {
    int e = blockIdx.x * blockDim.x + threadIdx.x;
    if (e >= E) return;
    int s = src[e];
    int d = dst[e];
    const float4* yr = (const float4*)(g_y + (size_t)s * ROWP);
    float4 a = __ldg(yr + 0);
    float4 b = __ldg(yr + 1);
    float4 c = __ldg(yr + 2);
    float* ap = g_acc + (size_t)d * ROWP;
    red_v4(ap + 0, a);
    red_v4(ap + 4, b);
    red_v4(ap + 8, c);
}

// ---------------- K4: per-node epilogue ----------------
__device__ __forceinline__ float fsigmoid(float x) {
    return 1.0f / (1.0f + __expf(-x));
}
__device__ __forceinline__ float ftanh(float x) {
    // tanh(x) = 1 - 2/(exp(2x)+1)
    return 1.0f - 2.0f / (1.0f + __expf(2.0f * x));
}

__global__ void k_final(const float* __restrict__ x,
                        const float* __restrict__ cz_w, const float* __restrict__ cz_b,
                        const float* __restrict__ lz_w, const float* __restrict__ lz_b,
                        const float* __restrict__ ch_w, const float* __restrict__ ch_b,
                        const float* __restrict__ lh_w, const float* __restrict__ lh_b,
                        const float* __restrict__ att,
                        const float* __restrict__ ow, const float* __restrict__ ob,
                        float* __restrict__ out, int n) {
    int i = blockIdx.x * blockDim.x + threadIdx.x;
    if (i >= n) return;

    // fold rank-1 GCN + linear into 4 affine coefficient pairs per gate
    float az[4], bz[4], ah[4], bh[4];
#pragma unroll
    for (int c = 0; c < 4; c++) {
        float a = 0.f, b = lz_b[c];
        float a2 = 0.f, b2 = lh_b[c];
#pragma unroll
        for (int k = 0; k < 4; k++) {
            float lz = lz_w[k * 4 + c];
            float lh = lh_w[k * 4 + c];
            a  += cz_w[k] * lz;
            b  += cz_b[k] * lz;
            a2 += ch_w[k] * lh;
            b2 += ch_b[k] * lh;
        }
        az[c] = a;  bz[c] = b;
        ah[c] = a2; bh[c] = b2;
    }

    // softmax over attention (12 values)
    float pr[NPER];
    float m = -1e30f;
#pragma unroll
    for (int p = 0; p < NPER; p++) m = fmaxf(m, att[p]);
    float sum = 0.f;
#pragma unroll
    for (int p = 0; p < NPER; p++) { pr[p] = __expf(att[p] - m); sum += pr[p]; }
    float inv = 1.0f / sum;
#pragma unroll
    for (int p = 0; p < NPER; p++) pr[p] *= inv;

    float dinv = g_dinv[i];
    float d2 = dinv * dinv;
    const float4* ar = (const float4*)(g_acc + (size_t)i * ROWP);
    const float4* xr = (const float4*)(x + (size_t)i * NPER);

    float s[NPER];
#pragma unroll
    for (int q = 0; q < 3; q++) {
        float4 av = ar[q];
        float4 xv = xr[q];
        s[q * 4 + 0] = dinv * av.x + d2 * xv.x;
        s[q * 4 + 1] = dinv * av.y + d2 * xv.y;
        s[q * 4 + 2] = dinv * av.z + d2 * xv.z;
        s[q * 4 + 3] = dinv * av.w + d2 * xv.w;
    }

    float H[4] = {0.f, 0.f, 0.f, 0.f};
#pragma unroll
    for (int p = 0; p < NPER; p++) {
        float sp = s[p];
        float w = pr[p];
#pragma unroll
        for (int c = 0; c < 4; c++) {
            float zc = fsigmoid(fmaf(sp, az[c], bz[c]));
            float th = ftanh(fmaf(sp, ah[c], bh[c]));
            H[c] = fmaf(w * (1.0f - zc), th, H[c]);
        }
    }

    // out = H @ out_w + out_b  → 12 floats
    float o[NPER];
#pragma unroll
    for (int f = 0; f < NPER; f++) {
        float v = ob[f];
#pragma unroll
        for (int c = 0; c < 4; c++) v = fmaf(H[c], ow[c * NPER + f], v);
        o[f] = v;
    }
    float4* orow = (float4*)(out + (size_t)i * NPER);
    orow[0] = make_float4(o[0], o[1], o[2], o[3]);
    orow[1] = make_float4(o[4], o[5], o[6], o[7]);
    orow[2] = make_float4(o[8], o[9], o[10], o[11]);
}

// ---------------- launch ----------------
extern "C" void kernel_launch(void* const* d_in, const int* in_sizes, int n_in,
                              void* d_out, int out_size) {
    const float* x  = (const float*)d_in[0];
    const int*   ei = (const int*)d_in[1];
    const float* cz_w = (const float*)d_in[2];
    const float* cz_b = (const float*)d_in[3];
    const float* lz_w = (const float*)d_in[4];
    const float* lz_b = (const float*)d_in[5];
    // d_in[6..9] = conv_r / lin_r : dead (multiplied by H0 == 0)
    const float* ch_w = (const float*)d_in[10];
    const float* ch_b = (const float*)d_in[11];
    const float* lh_w = (const float*)d_in[12];
    const float* lh_b = (const float*)d_in[13];
    const float* att  = (const float*)d_in[14];
    const float* ow   = (const float*)d_in[15];
    const float* ob   = (const float*)d_in[16];
    float* out = (float*)d_out;

    int N = in_sizes[0] / NPER;
    int E = in_sizes[1] / 2;
    const int* src = ei;
    const int* dst = ei + E;

    const int TB = 256;
    k_zero<<<(N * ROWP + TB - 1) / TB, TB>>>(N);
    int degThreads = (E >> 2) + 1;
    k_deg<<<(degThreads + TB - 1) / TB, TB>>>(dst, E);
    k_prep<<<(N + TB - 1) / TB, TB>>>(x, N);
    k_scatter<<<(E + TB - 1) / TB, TB>>>(src, dst, E);
    k_final<<<(N + TB - 1) / TB, TB>>>(x, cz_w, cz_b, lz_w, lz_b,
                                       ch_w, ch_b, lh_w, lh_b,
                                       att, ow, ob, out, N);
}

// round 3
// speedup vs baseline: 1.3839x; 1.3839x over previous
#include <cuda_runtime.h>
#include <cuda_fp16.h>

#define NODES_MAX 100000
#define NPER 12
#define ROWH 16   // padded fp16 row: 16 halves = 32 B = one L2 sector

__device__ int    g_deg[NODES_MAX];
__device__ float  g_dinv[NODES_MAX];
__device__ __half g_yh[NODES_MAX * ROWH];    // y = x * dinv_src, fp16
__device__ __half g_acch[NODES_MAX * ROWH];  // fp16 accumulator

// ---------------- K0: zero acc + deg ----------------
__global__ void k_zero(int n_nodes) {
    int i = blockIdx.x * blockDim.x + threadIdx.x;
    // acc: n_nodes*ROWH halves = n_nodes*2 uint4
    int accv = n_nodes * 2;
    if (i < accv) ((uint4*)g_acch)[i] = make_uint4(0, 0, 0, 0);
    if (i < n_nodes) g_deg[i] = 0;
}

// ---------------- K1: degree count (int4 vectorized) ----------------
__global__ void k_deg(const int* __restrict__ dst, int E) {
    int i = blockIdx.x * blockDim.x + threadIdx.x;
    int e4 = E >> 2;
    if (i < e4) {
        int4 d = ((const int4*)dst)[i];
        atomicAdd(&g_deg[d.x], 1);
        atomicAdd(&g_deg[d.y], 1);
        atomicAdd(&g_deg[d.z], 1);
        atomicAdd(&g_deg[d.w], 1);
    } else if (i == e4) {
        for (int r = e4 * 4; r < E; r++) atomicAdd(&g_deg[dst[r]], 1);
    }
}

// ---------------- K2: dinv + scaled x into padded fp16 rows ----------------
__global__ void k_prep(const float* __restrict__ x, int n) {
    int i = blockIdx.x * blockDim.x + threadIdx.x;
    if (i >= n) return;
    float dinv = rsqrtf((float)(g_deg[i] + 1));  // +1 for self loop
    g_dinv[i] = dinv;
    const float4* xr = (const float4*)(x + (size_t)i * NPER);
    float4 a = xr[0], b = xr[1], c = xr[2];
    __half2 h0 = __floats2half2_rn(a.x * dinv, a.y * dinv);
    __half2 h1 = __floats2half2_rn(a.z * dinv, a.w * dinv);
    __half2 h2 = __floats2half2_rn(b.x * dinv, b.y * dinv);
    __half2 h3 = __floats2half2_rn(b.z * dinv, b.w * dinv);
    __half2 h4 = __floats2half2_rn(c.x * dinv, c.y * dinv);
    __half2 h5 = __floats2half2_rn(c.z * dinv, c.w * dinv);
    uint4* row = (uint4*)(g_yh + (size_t)i * ROWH);
    uint4 lo;
    lo.x = *(unsigned*)&h0;
    lo.y = *(unsigned*)&h1;
    lo.z = *(unsigned*)&h2;
    lo.w = *(unsigned*)&h3;
    row[0] = lo;
    uint4 hi;
    hi.x = *(unsigned*)&h4;
    hi.y = *(unsigned*)&h5;
    hi.z = 0;
    hi.w = 0;
    row[1] = hi;
}

// ---------------- K3: edge scatter (the hot kernel) ----------------
__global__ void k_scatter(const int* __restrict__ src, const int* __restrict__ dst, int E) {
    int e = blockIdx.x * blockDim.x + threadIdx.x;
    if (e >= E) return;
    int s = src[e];
    int d = dst[e];
    const uint4* yr = (const uint4*)(g_yh + (size_t)s * ROWH);
    uint4 lo = __ldg(yr + 0);
    uint2 hi = __ldg((const uint2*)(yr + 1));
    __half* ap = g_acch + (size_t)d * ROWH;
    asm volatile("red.global.add.noftz.v4.f16x2 [%0], {%1,%2,%3,%4};"
                 :: "l"(ap), "r"(lo.x), "r"(lo.y), "r"(lo.z), "r"(lo.w)
                 : "memory");
    asm volatile("red.global.add.noftz.v2.f16x2 [%0], {%1,%2};"
                 :: "l"(ap + 8), "r"(hi.x), "r"(hi.y)
                 : "memory");
}

// ---------------- K4: per-node epilogue ----------------
__device__ __forceinline__ float fsigmoid(float x) {
    return 1.0f / (1.0f + __expf(-x));
}
__device__ __forceinline__ float ftanh(float x) {
    return 1.0f - 2.0f / (1.0f + __expf(2.0f * x));
}

__global__ void k_final(const float* __restrict__ x,
                        const float* __restrict__ cz_w, const float* __restrict__ cz_b,
                        const float* __restrict__ lz_w, const float* __restrict__ lz_b,
                        const float* __restrict__ ch_w, const float* __restrict__ ch_b,
                        const float* __restrict__ lh_w, const float* __restrict__ lh_b,
                        const float* __restrict__ att,
                        const float* __restrict__ ow, const float* __restrict__ ob,
                        float* __restrict__ out, int n) {
    int i = blockIdx.x * blockDim.x + threadIdx.x;
    if (i >= n) return;

    // fold rank-1 GCN + linear into 4 affine coefficient pairs per gate
    float az[4], bz[4], ah[4], bh[4];
#pragma unroll
    for (int c = 0; c < 4; c++) {
        float a = 0.f, b = lz_b[c];
        float a2 = 0.f, b2 = lh_b[c];
#pragma unroll
        for (int k = 0; k < 4; k++) {
            float lz = lz_w[k * 4 + c];
            float lh = lh_w[k * 4 + c];
            a  += cz_w[k] * lz;
            b  += cz_b[k] * lz;
            a2 += ch_w[k] * lh;
            b2 += ch_b[k] * lh;
        }
        az[c] = a;  bz[c] = b;
        ah[c] = a2; bh[c] = b2;
    }

    // softmax over attention (12 values)
    float pr[NPER];
    float m = -1e30f;
#pragma unroll
    for (int p = 0; p < NPER; p++) m = fmaxf(m, att[p]);
    float sum = 0.f;
#pragma unroll
    for (int p = 0; p < NPER; p++) { pr[p] = __expf(att[p] - m); sum += pr[p]; }
    float inv = 1.0f / sum;
#pragma unroll
    for (int p = 0; p < NPER; p++) pr[p] *= inv;

    float dinv = g_dinv[i];
    float d2 = dinv * dinv;

    const uint4* ar = (const uint4*)(g_acch + (size_t)i * ROWH);
    uint4 alo = ar[0];
    uint2 ahi = *(const uint2*)(ar + 1);
    float av[NPER];
    {
        float2 t;
        t = __half22float2(*(__half2*)&alo.x); av[0] = t.x; av[1] = t.y;
        t = __half22float2(*(__half2*)&alo.y); av[2] = t.x; av[3] = t.y;
        t = __half22float2(*(__half2*)&alo.z); av[4] = t.x; av[5] = t.y;
        t = __half22float2(*(__half2*)&alo.w); av[6] = t.x; av[7] = t.y;
        t = __half22float2(*(__half2*)&ahi.x); av[8] = t.x; av[9] = t.y;
        t = __half22float2(*(__half2*)&ahi.y); av[10] = t.x; av[11] = t.y;
    }

    const float4* xr = (const float4*)(x + (size_t)i * NPER);
    float xv[NPER];
#pragma unroll
    for (int q = 0; q < 3; q++) {
        float4 v = xr[q];
        xv[q * 4 + 0] = v.x; xv[q * 4 + 1] = v.y;
        xv[q * 4 + 2] = v.z; xv[q * 4 + 3] = v.w;
    }

    float H[4] = {0.f, 0.f, 0.f, 0.f};
#pragma unroll
    for (int p = 0; p < NPER; p++) {
        float sp = fmaf(dinv, av[p], d2 * xv[p]);  // edge sum + self loop (fp32)
        float w = pr[p];
#pragma unroll
        for (int c = 0; c < 4; c++) {
            float zc = fsigmoid(fmaf(sp, az[c], bz[c]));
            float th = ftanh(fmaf(sp, ah[c], bh[c]));
            H[c] = fmaf(w * (1.0f - zc), th, H[c]);
        }
    }

    // out = H @ out_w + out_b  → 12 floats
    float o[NPER];
#pragma unroll
    for (int f = 0; f < NPER; f++) {
        float v = ob[f];
#pragma unroll
        for (int c = 0; c < 4; c++) v = fmaf(H[c], ow[c * NPER + f], v);
        o[f] = v;
    }
    float4* orow = (float4*)(out + (size_t)i * NPER);
    orow[0] = make_float4(o[0], o[1], o[2], o[3]);
    orow[1] = make_float4(o[4], o[5], o[6], o[7]);
    orow[2] = make_float4(o[8], o[9], o[10], o[11]);
}

// ---------------- launch ----------------
extern "C" void kernel_launch(void* const* d_in, const int* in_sizes, int n_in,
                              void* d_out, int out_size) {
    const float* x  = (const float*)d_in[0];
    const int*   ei = (const int*)d_in[1];
    const float* cz_w = (const float*)d_in[2];
    const float* cz_b = (const float*)d_in[3];
    const float* lz_w = (const float*)d_in[4];
    const float* lz_b = (const float*)d_in[5];
    // d_in[6..9] = conv_r / lin_r : dead (multiplied by H0 == 0)
    const float* ch_w = (const float*)d_in[10];
    const float* ch_b = (const float*)d_in[11];
    const float* lh_w = (const float*)d_in[12];
    const float* lh_b = (const float*)d_in[13];
    const float* att  = (const float*)d_in[14];
    const float* ow   = (const float*)d_in[15];
    const float* ob   = (const float*)d_in[16];
    float* out = (float*)d_out;

    int N = in_sizes[0] / NPER;
    int E = in_sizes[1] / 2;
    const int* src = ei;
    const int* dst = ei + E;

    const int TB = 256;
    k_zero<<<(N * 2 + TB - 1) / TB, TB>>>(N);
    int degThreads = (E >> 2) + 1;
    k_deg<<<(degThreads + TB - 1) / TB, TB>>>(dst, E);
    k_prep<<<(N + TB - 1) / TB, TB>>>(x, N);
    k_scatter<<<(E + TB - 1) / TB, TB>>>(src, dst, E);
    k_final<<<(N + TB - 1) / TB, TB>>>(x, cz_w, cz_b, lz_w, lz_b,
                                       ch_w, ch_b, lh_w, lh_b,
                                       att, ow, ob, out, N);
}